// round 13
// baseline (speedup 1.0000x reference)
#include <cuda_runtime.h>
#include <cstdint>
#include <cstddef>

#define CIN   2112
#define COUT  192
#define NB    256
#define HW    49
#define G     2                 // batches per CTA
#define KT    16                // K per stage (2 k8 steps)
#define NITER (CIN / KT)        // 132
#define PIPE  4
#define THREADS 512
#define NMT   12                // m16 tiles
#define AS_T  (NMT * 2 * 32 * 4)     // 3072 floats per W stage (fragment-major)
#define BS_T  (G * 1024)             // 2048 floats per h stage (fragment-major)
#define SMEM_BYTES (PIPE * (AS_T + BS_T) * 4)   // 81920

// device scratch (alloc-free rules)
__device__ float2 g_ss[CIN];                        // {scale, shift}
__device__ __align__(16) float g_Wp[COUT * CIN];    // fragment-major tf32 W

__device__ __forceinline__ uint32_t f2tf32(float f) {
    uint32_t t; asm("cvt.rna.tf32.f32 %0, %1;" : "=r"(t) : "f"(f)); return t;
}

// g_Wp slot s (4 floats): lane=s&31; t=s>>5; kk=t&1; mt=(t>>1)%12; kt=(t>>1)/12
__global__ void prep_kernel(const float* __restrict__ gamma,
                            const float* __restrict__ beta,
                            const float* __restrict__ rmean,
                            const float* __restrict__ rvar,
                            const float* __restrict__ W) {
    int tid = blockIdx.x * blockDim.x + threadIdx.x;
    if (tid < CIN) {
        float inv = rsqrtf(rvar[tid] + 1e-5f);
        float sc  = gamma[tid] * inv;
        g_ss[tid] = make_float2(sc, beta[tid] - rmean[tid] * sc);
    }
    const int total = (COUT * CIN) / 4;
    for (int s = tid; s < total; s += gridDim.x * blockDim.x) {
        int lane = s & 31;
        int t    = s >> 5;
        int kk   = t & 1;
        int mtt  = t >> 1;
        int mt   = mtt % NMT;
        int kt   = mtt / NMT;
        int gr   = lane >> 2;
        int ct   = lane & 3;
        int k    = kt * KT + kk * 8 + ct;
        int r0   = mt * 16 + gr;
        float* dst = g_Wp + (size_t)s * 4;
        dst[0] = __uint_as_float(f2tf32(W[(size_t)r0       * CIN + k]));
        dst[1] = __uint_as_float(f2tf32(W[(size_t)(r0 + 8) * CIN + k]));
        dst[2] = __uint_as_float(f2tf32(W[(size_t)r0       * CIN + k + 4]));
        dst[3] = __uint_as_float(f2tf32(W[(size_t)(r0 + 8) * CIN + k + 4]));
    }
}

__device__ __forceinline__ void cp_async16(uint32_t dst, const void* src) {
    asm volatile("cp.async.cg.shared.global [%0], [%1], 16;" :: "r"(dst), "l"(src));
}
__device__ __forceinline__ void mma_tf32(float* d, const uint32_t* a, uint32_t b0, uint32_t b1) {
    asm volatile(
        "mma.sync.aligned.m16n8k8.row.col.f32.tf32.tf32.f32 "
        "{%0,%1,%2,%3}, {%4,%5,%6,%7}, {%8,%9}, {%0,%1,%2,%3};\n"
        : "+f"(d[0]), "+f"(d[1]), "+f"(d[2]), "+f"(d[3])
        : "r"(a[0]), "r"(a[1]), "r"(a[2]), "r"(a[3]), "r"(b0), "r"(b1));
}

// B fragments: bq[(kk*4 + wn*2 + q)*32 + lane] = {b0(j0), b1(j0), b0(j1), b1(j1)}
// for j = (wn*2+q)*2 + {0,1};  b0 = h[8kk+ct][j*8+gr], b1 = h[8kk+4+ct][j*8+gr]
template<int JCNT>
__device__ __forceinline__ void computeTile(const uint4* __restrict__ asp,
                                            const uint4* __restrict__ bq,
                                            int lane, int wm, int wn,
                                            float acc[3][4][4]) {
    #pragma unroll
    for (int kk = 0; kk < 2; kk++) {
        uint4 a[3];
        #pragma unroll
        for (int i = 0; i < 3; i++)
            a[i] = asp[((wm * 3 + i) * 2 + kk) * 32 + lane];
        uint4 bf[2];
        #pragma unroll
        for (int q = 0; q < 2; q++)
            bf[q] = bq[(kk * 4 + wn * 2 + q) * 32 + lane];
        #pragma unroll
        for (int jj = 0; jj < JCNT; jj++) {
            const int q = jj >> 1;
            const uint32_t b0 = (jj & 1) ? bf[q].z : bf[q].x;
            const uint32_t b1 = (jj & 1) ? bf[q].w : bf[q].y;
            #pragma unroll
            for (int i = 0; i < 3; i++)
                mma_tf32(acc[i][jj], (const uint32_t*)&a[i], b0, b1);
        }
    }
}

__global__ __launch_bounds__(THREADS, 1)
void gemm_kernel(const float* __restrict__ x, float* __restrict__ out) {
    extern __shared__ __align__(16) float smem[];
    float* Asm = smem;                     // PIPE * AS_T
    float* Bsm = smem + PIPE * AS_T;       // PIPE * BS_T

    const int tid  = threadIdx.x;
    const int lane = tid & 31;
    const int w    = tid >> 5;
    const int gr   = lane >> 2;
    const int ct   = lane & 3;
    const int wg   = w >> 3;          // batch
    const int wr   = w & 7;
    const int wm   = wr >> 1;         // m-group (3 m16 tiles)
    const int wn   = wr & 1;          // n-group
    const int batch0 = blockIdx.x * G;

    // ---- producer geometry: thread handles channel-pair (clo, clo+4) at pos, both batches
    const int grp  = tid & 7;
    const int ctp  = (tid >> 3) & 3;
    const int j01  = (tid >> 5) & 1;
    const int jpp  = (tid >> 6) & 3;
    const int kkp  = (tid >> 8) & 1;
    const int pos  = jpp * 16 + j01 * 8 + grp;
    const bool ok  = (pos < HW);
    const int clo  = kkp * 8 + ctp;                 // channel-in-stage, hi = clo+4
    const int sidx2 = ((kkp * 4 + jpp) * 32 + grp * 4 + ctp) * 2 + j01;  // float2 units

    const float* xp[4];
    #pragma unroll
    for (int i = 0; i < 2; i++)
        #pragma unroll
        for (int h = 0; h < 2; h++)
            xp[i * 2 + h] = x + ((size_t)(batch0 + i) * CIN + clo + 4 * h) * HW + pos;

    float acc[3][4][4];
    #pragma unroll
    for (int i = 0; i < 3; i++)
        #pragma unroll
        for (int j = 0; j < 4; j++)
            #pragma unroll
            for (int q = 0; q < 4; q++) acc[i][j][q] = 0.0f;

    float xr[4], xr2[4];

    auto loadX = [&](int stage, float* dst) {
        const int off = stage * KT * HW;
        #pragma unroll
        for (int k = 0; k < 4; k++)
            dst[k] = ok ? __ldg(xp[k] + off) : 0.0f;
    };
    auto stsB = [&](int stage) {
        const float2 ssl = g_ss[stage * KT + clo];
        const float2 ssh = g_ss[stage * KT + clo + 4];
        float2* bb = (float2*)(Bsm + (stage & 3) * BS_T);
        #pragma unroll
        for (int i = 0; i < 2; i++) {
            float h0 = fmaxf(fmaf(xr[i * 2],     ssl.x, ssl.y), 0.0f);
            float h1 = fmaxf(fmaf(xr[i * 2 + 1], ssh.x, ssh.y), 0.0f);
            uint32_t t0 = ok ? f2tf32(h0) : 0u;
            uint32_t t1 = ok ? f2tf32(h1) : 0u;
            bb[i * 512 + sidx2] = make_float2(__uint_as_float(t0), __uint_as_float(t1));
        }
    };
    auto fillAs = [&](int stage) {
        const float* src = g_Wp + (size_t)stage * AS_T;
        float* dst = Asm + (stage & 3) * AS_T;
        {
            int o = tid;
            cp_async16((uint32_t)__cvta_generic_to_shared(dst + o * 4), src + (size_t)o * 4);
        }
        if (tid < AS_T / 4 - THREADS) {
            int o = THREADS + tid;
            cp_async16((uint32_t)__cvta_generic_to_shared(dst + o * 4), src + (size_t)o * 4);
        }
        asm volatile("cp.async.commit_group;");
    };

    // ---- prologue ----
    #pragma unroll
    for (int ps = 0; ps < 3; ps++) {
        loadX(ps, xr);
        stsB(ps);
        fillAs(ps);
    }
    loadX(3, xr);

    // ---- main loop: one sync per stage ----
    for (int s = 0; s < NITER; s++) {
        if (s < NITER - 2)       asm volatile("cp.async.wait_group 2;");
        else if (s == NITER - 2) asm volatile("cp.async.wait_group 1;");
        else                     asm volatile("cp.async.wait_group 0;");
        __syncthreads();

        if (s + 3 < NITER) fillAs(s + 3);
        if (s + 4 < NITER) loadX(s + 4, xr2);
        if (s + 3 < NITER) stsB(s + 3);

        const uint4* asp = (const uint4*)(Asm + (s & 3) * AS_T);
        const uint4* bq  = (const uint4*)(Bsm + (s & 3) * BS_T + wg * 1024);
        if (wn == 0) computeTile<4>(asp, bq, lane, wm, wn, acc);
        else         computeTile<3>(asp, bq, lane, wm, wn, acc);

        #pragma unroll
        for (int i = 0; i < 4; i++) xr[i] = xr2[i];
    }

    // ---- epilogue ----
    const int jcnt = wn ? 3 : 4;
    const int jlo  = wn * 4;
    float* ob = out + (size_t)(batch0 + wg) * COUT * HW;
    #pragma unroll
    for (int i = 0; i < 3; i++) {
        const int m  = (wm * 3 + i) * 16;
        const int r0 = m + gr, r1 = m + gr + 8;
        #pragma unroll
        for (int jj = 0; jj < 4; jj++) {
            if (jj >= jcnt) break;
            const int n0 = (jlo + jj) * 8 + 2 * ct;
            if (n0 < HW) {
                ob[r0 * HW + n0] = acc[i][jj][0];
                ob[r1 * HW + n0] = acc[i][jj][2];
            }
            if (n0 + 1 < HW) {
                ob[r0 * HW + n0 + 1] = acc[i][jj][1];
                ob[r1 * HW + n0 + 1] = acc[i][jj][3];
            }
        }
    }
}

extern "C" void kernel_launch(void* const* d_in, const int* in_sizes, int n_in,
                              void* d_out, int out_size) {
    const float* x     = (const float*)d_in[0];
    const float* gamma = (const float*)d_in[1];
    const float* beta  = (const float*)d_in[2];
    const float* rmean = (const float*)d_in[3];
    const float* rvar  = (const float*)d_in[4];
    const float* W     = (const float*)d_in[5];
    float* out = (float*)d_out;

    prep_kernel<<<132, 512>>>(gamma, beta, rmean, rvar, W);

    cudaFuncSetAttribute(gemm_kernel, cudaFuncAttributeMaxDynamicSharedMemorySize, SMEM_BYTES);
    gemm_kernel<<<NB / G, THREADS, SMEM_BYTES>>>(x, out);
}

// round 15
// speedup vs baseline: 1.5622x; 1.5622x over previous
#include <cuda_runtime.h>
#include <cstdint>
#include <cstddef>

#define CIN   2112
#define COUT  192
#define NB    256
#define HW    49
#define KT    16                // K per stage (2 k8 steps)
#define NITER (CIN / KT)        // 132
#define PIPE  4
#define THREADS 256
#define NMT   12                // m16 tiles
#define BSTRIDE 72              // Bs row stride (floats): banks 8ct+8j+gr -> conflict-free
#define AS_T  (NMT * 2 * 32 * 4)     // 3072 floats per W stage (fragment-major)
#define BS_T  (KT * BSTRIDE)         // 1152 floats per h stage (one batch)
#define SMEM_BYTES (PIPE * (AS_T + BS_T) * 4)   // 67584

// device scratch (alloc-free rules)
__device__ float2 g_ss[CIN];                       // {scale, shift}
__device__ __align__(16) float g_Wp[COUT * CIN];   // fragment-major tf32 W

__device__ __forceinline__ uint32_t f2tf32(float f) {
    uint32_t t; asm("cvt.rna.tf32.f32 %0, %1;" : "=r"(t) : "f"(f)); return t;
}

// g_Wp slot s (4 floats): lane=s&31; t=s>>5; kk=t&1; mt=(t>>1)%12; kt=(t>>1)/12
__global__ void prep_kernel(const float* __restrict__ gamma,
                            const float* __restrict__ beta,
                            const float* __restrict__ rmean,
                            const float* __restrict__ rvar,
                            const float* __restrict__ W) {
    int tid = blockIdx.x * blockDim.x + threadIdx.x;
    if (tid < CIN) {
        float inv = rsqrtf(rvar[tid] + 1e-5f);
        float sc  = gamma[tid] * inv;
        g_ss[tid] = make_float2(sc, beta[tid] - rmean[tid] * sc);
    }
    const int total = (COUT * CIN) / 4;
    for (int s = tid; s < total; s += gridDim.x * blockDim.x) {
        int lane = s & 31;
        int t    = s >> 5;
        int kk   = t & 1;
        int mtt  = t >> 1;
        int mt   = mtt % NMT;
        int kt   = mtt / NMT;
        int gr   = lane >> 2;
        int ct   = lane & 3;
        int k    = kt * KT + kk * 8 + ct;
        int r0   = mt * 16 + gr;
        float* dst = g_Wp + (size_t)s * 4;
        dst[0] = __uint_as_float(f2tf32(W[(size_t)r0       * CIN + k]));
        dst[1] = __uint_as_float(f2tf32(W[(size_t)(r0 + 8) * CIN + k]));
        dst[2] = __uint_as_float(f2tf32(W[(size_t)r0       * CIN + k + 4]));
        dst[3] = __uint_as_float(f2tf32(W[(size_t)(r0 + 8) * CIN + k + 4]));
    }
}

__device__ __forceinline__ void cp_async16(uint32_t dst, const void* src) {
    asm volatile("cp.async.cg.shared.global [%0], [%1], 16;" :: "r"(dst), "l"(src));
}
__device__ __forceinline__ void mma_tf32(float* d, const uint32_t* a, uint32_t b0, uint32_t b1) {
    asm volatile(
        "mma.sync.aligned.m16n8k8.row.col.f32.tf32.tf32.f32 "
        "{%0,%1,%2,%3}, {%4,%5,%6,%7}, {%8,%9}, {%0,%1,%2,%3};\n"
        : "+f"(d[0]), "+f"(d[1]), "+f"(d[2]), "+f"(d[3])
        : "r"(a[0]), "r"(a[1]), "r"(a[2]), "r"(a[3]), "r"(b0), "r"(b1));
}

template<int JCNT>
__device__ __forceinline__ void computeTile(const uint4* __restrict__ asp,
                                            const float* __restrict__ bsp,
                                            int lane, int gr, int ct, int wm, int jlo,
                                            float acc[3][4][4]) {
    #pragma unroll
    for (int kk = 0; kk < 2; kk++) {
        uint4 a[3];
        #pragma unroll
        for (int i = 0; i < 3; i++) {
            int mt = wm * 3 + i;
            a[i] = asp[(mt * 2 + kk) * 32 + lane];
        }
        #pragma unroll
        for (int jj = 0; jj < JCNT; jj++) {
            int j = jlo + jj;
            uint32_t b0 = __float_as_uint(bsp[(kk * 8 + ct)     * BSTRIDE + j * 8 + gr]);
            uint32_t b1 = __float_as_uint(bsp[(kk * 8 + ct + 4) * BSTRIDE + j * 8 + gr]);
            #pragma unroll
            for (int i = 0; i < 3; i++)
                mma_tf32(acc[i][jj], (const uint32_t*)&a[i], b0, b1);
        }
    }
}

__global__ __launch_bounds__(THREADS, 2)
void gemm_kernel(const float* __restrict__ x, float* __restrict__ out) {
    extern __shared__ __align__(16) float smem[];
    float* Asm = smem;                     // PIPE * AS_T
    float* Bsm = smem + PIPE * AS_T;       // PIPE * BS_T

    const int tid  = threadIdx.x;
    const int lane = tid & 31;
    const int w    = tid >> 5;
    const int gr   = lane >> 2;
    const int ct   = lane & 3;
    const int wm   = w >> 1;          // m-group (3 m16 tiles)
    const int wn   = w & 1;           // n-group: 4 or 3 n8 tiles
    const int jlo  = wn * 4;
    const int batch = blockIdx.x;     // one batch per CTA

    // per-thread x/B geometry: idx = tid + i*256 in [0,1024): row=idx>>6 (kr), col=idx&63
    bool ld_ok[4]; int ld_sidx[4], ld_kr[4];
    const float* ld_base[4];
    #pragma unroll
    for (int i = 0; i < 4; i++) {
        int idx = tid + i * THREADS;
        int row = idx >> 6;           // kr 0..15
        int col = idx & 63;
        ld_ok[i]   = (col < HW);
        ld_kr[i]   = row;
        ld_sidx[i] = row * BSTRIDE + col;
        ld_base[i] = x + ((size_t)batch * CIN + row) * HW + col;
    }

    float acc[3][4][4];
    #pragma unroll
    for (int i = 0; i < 3; i++)
        #pragma unroll
        for (int j = 0; j < 4; j++)
            #pragma unroll
            for (int q = 0; q < 4; q++) acc[i][j][q] = 0.0f;

    float xr[4], xr2[4];

    auto loadX = [&](int stage, float* dst) {
        const int off = stage * KT * HW;
        #pragma unroll
        for (int i = 0; i < 4; i++)
            dst[i] = ld_ok[i] ? __ldg(ld_base[i] + off) : 0.0f;
    };
    auto stsB = [&](int stage) {
        float* bdst = Bsm + (stage & 3) * BS_T;
        const int k0 = stage * KT;
        #pragma unroll
        for (int i = 0; i < 4; i++) {
            uint32_t t = 0u;
            if (ld_ok[i]) {
                const float2 ss = __ldg(&g_ss[k0 + ld_kr[i]]);
                float h = fmaxf(fmaf(xr[i], ss.x, ss.y), 0.0f);
                t = f2tf32(h);
            }
            bdst[ld_sidx[i]] = __uint_as_float(t);
        }
    };
    auto fillAs = [&](int stage) {   // 768 float4 per stage, 3 per thread
        const float* src = g_Wp + (size_t)stage * AS_T;
        float* dst = Asm + (stage & 3) * AS_T;
        #pragma unroll
        for (int i = 0; i < 3; i++) {
            int o = tid + i * THREADS;
            cp_async16((uint32_t)__cvta_generic_to_shared(dst + o * 4), src + (size_t)o * 4);
        }
        asm volatile("cp.async.commit_group;");
    };

    // ---- prologue: stages 0..2 staged, stage 3 x in regs ----
    #pragma unroll
    for (int ps = 0; ps < 3; ps++) {
        loadX(ps, xr);
        stsB(ps);
        fillAs(ps);
    }
    loadX(3, xr);

    // ---- main loop: one sync per stage ----
    for (int s = 0; s < NITER; s++) {
        if (s < NITER - 2)       asm volatile("cp.async.wait_group 2;");
        else if (s == NITER - 2) asm volatile("cp.async.wait_group 1;");
        else                     asm volatile("cp.async.wait_group 0;");
        __syncthreads();

        if (s + 3 < NITER) fillAs(s + 3);
        if (s + 4 < NITER) loadX(s + 4, xr2);
        if (s + 3 < NITER) stsB(s + 3);

        const uint4*  asp = (const uint4*)(Asm + (s & 3) * AS_T);
        const float*  bsp = Bsm + (s & 3) * BS_T;
        if (wn == 0) computeTile<4>(asp, bsp, lane, gr, ct, wm, jlo, acc);
        else         computeTile<3>(asp, bsp, lane, gr, ct, wm, jlo, acc);

        #pragma unroll
        for (int i = 0; i < 4; i++) xr[i] = xr2[i];
    }

    // ---- epilogue ----
    const int jcnt = wn ? 3 : 4;
    float* ob = out + (size_t)batch * COUT * HW;
    #pragma unroll
    for (int i = 0; i < 3; i++) {
        const int m  = (wm * 3 + i) * 16;
        const int r0 = m + gr, r1 = m + gr + 8;
        #pragma unroll
        for (int jj = 0; jj < 4; jj++) {
            if (jj >= jcnt) break;
            const int n0 = (jlo + jj) * 8 + 2 * ct;
            if (n0 < HW) {
                ob[r0 * HW + n0] = acc[i][jj][0];
                ob[r1 * HW + n0] = acc[i][jj][2];
            }
            if (n0 + 1 < HW) {
                ob[r0 * HW + n0 + 1] = acc[i][jj][1];
                ob[r1 * HW + n0 + 1] = acc[i][jj][3];
            }
        }
    }
}

extern "C" void kernel_launch(void* const* d_in, const int* in_sizes, int n_in,
                              void* d_out, int out_size) {
    const float* x     = (const float*)d_in[0];
    const float* gamma = (const float*)d_in[1];
    const float* beta  = (const float*)d_in[2];
    const float* rmean = (const float*)d_in[3];
    const float* rvar  = (const float*)d_in[4];
    const float* W     = (const float*)d_in[5];
    float* out = (float*)d_out;

    prep_kernel<<<132, 512>>>(gamma, beta, rmean, rvar, W);

    cudaFuncSetAttribute(gemm_kernel, cudaFuncAttributeMaxDynamicSharedMemorySize, SMEM_BYTES);
    gemm_kernel<<<NB, THREADS, SMEM_BYTES>>>(x, out);
}

// round 16
// speedup vs baseline: 1.7564x; 1.1243x over previous
#include <cuda_runtime.h>
#include <cstdint>
#include <cstddef>

#define CIN   2112
#define COUT  192
#define NB    256
#define HW    49
#define KT    32                // K per stage (4 k8 steps)
#define NITER (CIN / KT)        // 66
#define PIPE  3
#define THREADS 256
#define NMT   12                // m16 tiles
#define BSTRIDE 72              // Bs row stride (floats): banks ct*8+gr -> conflict-free
#define AS_T  (NMT * 4 * 32 * 4)     // 6144 floats per W stage (fragment-major)
#define BS_T  (KT * BSTRIDE)         // 2304 floats per h stage (one batch)
#define STAGE_T (AS_T + BS_T)        // 8448 floats
#define SMEM_BYTES (PIPE * STAGE_T * 4)   // 101376

// device scratch (alloc-free rules)
__device__ float2 g_ss[CIN];                       // {scale, shift}
__device__ __align__(16) float g_Wp[COUT * CIN];   // fragment-major tf32 W

__device__ __forceinline__ uint32_t f2tf32(float f) {
    uint32_t t; asm("cvt.rna.tf32.f32 %0, %1;" : "=r"(t) : "f"(f)); return t;
}

// g_Wp slot s (4 floats): lane=s&31; t=s>>5; kk=t&3; mt=(t>>2)%12; kt=(t>>2)/12
// holds A-fragment {a0,a1,a2,a3} of m16n8k8 tile (mt, k = kt*32 + kk*8)
__global__ void prep_kernel(const float* __restrict__ gamma,
                            const float* __restrict__ beta,
                            const float* __restrict__ rmean,
                            const float* __restrict__ rvar,
                            const float* __restrict__ W) {
    int tid = blockIdx.x * blockDim.x + threadIdx.x;
    if (tid < CIN) {
        float inv = rsqrtf(rvar[tid] + 1e-5f);
        float sc  = gamma[tid] * inv;
        g_ss[tid] = make_float2(sc, beta[tid] - rmean[tid] * sc);
    }
    const int total = (COUT * CIN) / 4;
    for (int s = tid; s < total; s += gridDim.x * blockDim.x) {
        int lane = s & 31;
        int t    = s >> 5;
        int kk   = t & 3;
        int mtt  = t >> 2;
        int mt   = mtt % NMT;
        int kt   = mtt / NMT;
        int gr   = lane >> 2;
        int ct   = lane & 3;
        int k    = kt * KT + kk * 8 + ct;
        int r0   = mt * 16 + gr;
        float* dst = g_Wp + (size_t)s * 4;
        dst[0] = __uint_as_float(f2tf32(W[(size_t)r0       * CIN + k]));
        dst[1] = __uint_as_float(f2tf32(W[(size_t)(r0 + 8) * CIN + k]));
        dst[2] = __uint_as_float(f2tf32(W[(size_t)r0       * CIN + k + 4]));
        dst[3] = __uint_as_float(f2tf32(W[(size_t)(r0 + 8) * CIN + k + 4]));
    }
}

__device__ __forceinline__ void cp_async16(uint32_t dst, const void* src) {
    asm volatile("cp.async.cg.shared.global [%0], [%1], 16;" :: "r"(dst), "l"(src));
}
__device__ __forceinline__ void mma_tf32(float* d, const uint32_t* a, uint32_t b0, uint32_t b1) {
    asm volatile(
        "mma.sync.aligned.m16n8k8.row.col.f32.tf32.tf32.f32 "
        "{%0,%1,%2,%3}, {%4,%5,%6,%7}, {%8,%9}, {%0,%1,%2,%3};\n"
        : "+f"(d[0]), "+f"(d[1]), "+f"(d[2]), "+f"(d[3])
        : "r"(a[0]), "r"(a[1]), "r"(a[2]), "r"(a[3]), "r"(b0), "r"(b1));
}

template<int JCNT>
__device__ __forceinline__ void computeTile(const uint4* __restrict__ asp,
                                            const float* __restrict__ bsp,
                                            int lane, int gr, int ct, int wm, int jlo,
                                            float acc[3][4][4]) {
    #pragma unroll
    for (int kk = 0; kk < 4; kk++) {
        uint4 a[3];
        #pragma unroll
        for (int i = 0; i < 3; i++) {
            int mt = wm * 3 + i;
            a[i] = asp[(mt * 4 + kk) * 32 + lane];
        }
        #pragma unroll
        for (int jj = 0; jj < JCNT; jj++) {
            int j = jlo + jj;
            uint32_t b0 = __float_as_uint(bsp[(kk * 8 + ct)     * BSTRIDE + j * 8 + gr]);
            uint32_t b1 = __float_as_uint(bsp[(kk * 8 + ct + 4) * BSTRIDE + j * 8 + gr]);
            #pragma unroll
            for (int i = 0; i < 3; i++)
                mma_tf32(acc[i][jj], (const uint32_t*)&a[i], b0, b1);
        }
    }
}

__global__ __launch_bounds__(THREADS, 2)
void gemm_kernel(const float* __restrict__ x, float* __restrict__ out) {
    extern __shared__ __align__(16) float smem[];

    const int tid  = threadIdx.x;
    const int lane = tid & 31;
    const int w    = tid >> 5;
    const int gr   = lane >> 2;
    const int ct   = lane & 3;
    const int wm   = w >> 1;          // m-group (3 m16 tiles)
    const int wn   = w & 1;           // n-group: 4 or 3 n8 tiles
    const int jlo  = wn * 4;
    const int batch = blockIdx.x;     // one batch per CTA

    // x geometry: col = tid&63 (i-invariant), row_i = (tid>>6) + 4*i  (i = 0..7)
    const int col  = tid & 63;
    const int row0 = tid >> 6;        // 0..3
    const bool ok  = (col < HW);
    const float* xbase = x + (size_t)batch * CIN * HW + (size_t)row0 * HW + col;

    float acc[3][4][4];
    #pragma unroll
    for (int i = 0; i < 3; i++)
        #pragma unroll
        for (int j = 0; j < 4; j++)
            #pragma unroll
            for (int q = 0; q < 4; q++) acc[i][j][q] = 0.0f;

    float xr[8], xr2[8];

    auto loadX = [&](int stage, float* dst) {
        const float* p = xbase + (size_t)stage * KT * HW;
        #pragma unroll
        for (int i = 0; i < 8; i++)
            dst[i] = ok ? __ldg(p + (size_t)(4 * i) * HW) : 0.0f;
    };
    auto stsB = [&](int stage) {
        float* bdst = smem + (stage % PIPE) * STAGE_T + AS_T;
        const int k0 = stage * KT + row0;
        #pragma unroll
        for (int i = 0; i < 8; i++) {
            uint32_t t = 0u;
            if (ok) {
                const float2 ss = __ldg(&g_ss[k0 + 4 * i]);
                float h = fmaxf(fmaf(xr[i], ss.x, ss.y), 0.0f);
                t = f2tf32(h);
            }
            bdst[(row0 + 4 * i) * BSTRIDE + col] = __uint_as_float(t);
        }
    };
    auto fillAs = [&](int stage) {   // 1536 float4 per stage, 6 per thread
        const float* src = g_Wp + (size_t)stage * AS_T;
        float* dst = smem + (stage % PIPE) * STAGE_T;
        #pragma unroll
        for (int i = 0; i < 6; i++) {
            int o = tid + i * THREADS;
            cp_async16((uint32_t)__cvta_generic_to_shared(dst + o * 4), src + (size_t)o * 4);
        }
        asm volatile("cp.async.commit_group;");
    };

    // ---- prologue: stages 0,1 staged; stage 2 x in regs ----
    loadX(0, xr); stsB(0); fillAs(0);
    loadX(1, xr); stsB(1); fillAs(1);
    loadX(2, xr);

    // ---- main loop: one sync per 32-K stage ----
    for (int s = 0; s < NITER; s++) {
        if (s < NITER - 1) asm volatile("cp.async.wait_group 1;");
        else               asm volatile("cp.async.wait_group 0;");
        __syncthreads();

        if (s + 2 < NITER) fillAs(s + 2);
        if (s + 3 < NITER) loadX(s + 3, xr2);
        if (s + 2 < NITER) stsB(s + 2);

        const uint4*  asp = (const uint4*)(smem + (s % PIPE) * STAGE_T);
        const float*  bsp = smem + (s % PIPE) * STAGE_T + AS_T;
        if (wn == 0) computeTile<4>(asp, bsp, lane, gr, ct, wm, jlo, acc);
        else         computeTile<3>(asp, bsp, lane, gr, ct, wm, jlo, acc);

        #pragma unroll
        for (int i = 0; i < 8; i++) xr[i] = xr2[i];
    }

    // ---- epilogue ----
    const int jcnt = wn ? 3 : 4;
    float* ob = out + (size_t)batch * COUT * HW;
    #pragma unroll
    for (int i = 0; i < 3; i++) {
        const int m  = (wm * 3 + i) * 16;
        const int r0 = m + gr, r1 = m + gr + 8;
        #pragma unroll
        for (int jj = 0; jj < 4; jj++) {
            if (jj >= jcnt) break;
            const int n0 = (jlo + jj) * 8 + 2 * ct;
            if (n0 < HW) {
                ob[r0 * HW + n0] = acc[i][jj][0];
                ob[r1 * HW + n0] = acc[i][jj][2];
            }
            if (n0 + 1 < HW) {
                ob[r0 * HW + n0 + 1] = acc[i][jj][1];
                ob[r1 * HW + n0 + 1] = acc[i][jj][3];
            }
        }
    }
}

extern "C" void kernel_launch(void* const* d_in, const int* in_sizes, int n_in,
                              void* d_out, int out_size) {
    const float* x     = (const float*)d_in[0];
    const float* gamma = (const float*)d_in[1];
    const float* beta  = (const float*)d_in[2];
    const float* rmean = (const float*)d_in[3];
    const float* rvar  = (const float*)d_in[4];
    const float* W     = (const float*)d_in[5];
    float* out = (float*)d_out;

    prep_kernel<<<132, 512>>>(gamma, beta, rmean, rvar, W);

    cudaFuncSetAttribute(gemm_kernel, cudaFuncAttributeMaxDynamicSharedMemorySize, SMEM_BYTES);
    gemm_kernel<<<NB, THREADS, SMEM_BYTES>>>(x, out);
}